// round 8
// baseline (speedup 1.0000x reference)
#include <cuda_runtime.h>
#include <cuda_bf16.h>

// Persistent fused kernel: 4736 CTAs x 64 threads (4 item-slots x 16 lanes).
// Each CTA grid-strides over ~3-4 rows; no inter-wave drain.

#define NCTA 4736

__global__ __launch_bounds__(64)
void svdpp_kernel(const int* __restrict__ user_ids,
                  const int* __restrict__ item_ids,
                  const int* __restrict__ offsets,
                  const int* __restrict__ flat_implicit,
                  const float4* __restrict__ user_emb4,
                  const float4* __restrict__ item_emb4,
                  const float4* __restrict__ imp_emb4,
                  const float* __restrict__ user_bias,
                  const float* __restrict__ item_bias,
                  const float* __restrict__ global_bias,
                  float* __restrict__ out,
                  int B, int N) {
    const int tid  = threadIdx.x;
    const int lane = tid & 15;          // float4 index within 256B row
    const int slot = tid >> 4;          // item slot 0..3

    const float gb = __ldg(&global_bias[0]);
    __shared__ float4 s[16];

    for (int b = blockIdx.x; b < B; b += NCTA) {
        const int start = __ldg(&offsets[b]);
        const int end   = (b + 1 < B) ? __ldg(&offsets[b + 1]) : N;
        const int len   = end - start;

        // Epilogue operands issued early; latency hides under the gather.
        const int u  = __ldg(&user_ids[b]);
        const int it = __ldg(&item_ids[b]);
        const float4 u4 = __ldg(&user_emb4[(size_t)u * 16 + lane]);
        const float4 i4 = __ldg(&item_emb4[(size_t)it * 16 + lane]);
        const float  ub = __ldg(&user_bias[u]);
        const float  ib = __ldg(&item_bias[it]);

        float4 acc = make_float4(0.f, 0.f, 0.f, 0.f);

        int j = start + slot;
        // 2 independent row-gathers in flight per thread (8 per row).
        for (; j + 4 < end; j += 8) {
            const int i0 = __ldg(&flat_implicit[j]);
            const int i1 = __ldg(&flat_implicit[j + 4]);
            const float4 a0 = __ldg(&imp_emb4[(size_t)i0 * 16 + lane]);
            const float4 a1 = __ldg(&imp_emb4[(size_t)i1 * 16 + lane]);
            acc.x += a0.x + a1.x;
            acc.y += a0.y + a1.y;
            acc.z += a0.z + a1.z;
            acc.w += a0.w + a1.w;
        }
        if (j < end) {
            const float4 a = __ldg(&imp_emb4[(size_t)__ldg(&flat_implicit[j]) * 16 + lane]);
            acc.x += a.x; acc.y += a.y; acc.z += a.z; acc.w += a.w;
        }

        // Combine slots 0/1 (warp 0) and 2/3 (warp 1).
        acc.x += __shfl_xor_sync(0xffffffffu, acc.x, 16);
        acc.y += __shfl_xor_sync(0xffffffffu, acc.y, 16);
        acc.z += __shfl_xor_sync(0xffffffffu, acc.z, 16);
        acc.w += __shfl_xor_sync(0xffffffffu, acc.w, 16);

        if (tid >= 32 && tid < 48) s[lane] = acc;   // warp 1 -> smem
        __syncthreads();

        if (tid < 16) {
            const float4 o = s[tid];
            acc.x += o.x; acc.y += o.y; acc.z += o.z; acc.w += o.w;

            const float invnorm = (len > 0) ? rsqrtf((float)len) : 1.0f;

            float dot = (u4.x + acc.x * invnorm) * i4.x
                      + (u4.y + acc.y * invnorm) * i4.y
                      + (u4.z + acc.z * invnorm) * i4.z
                      + (u4.w + acc.w * invnorm) * i4.w;

            #pragma unroll
            for (int off = 8; off > 0; off >>= 1)
                dot += __shfl_down_sync(0x0000ffffu, dot, off);

            if (tid == 0)
                out[b] = dot + ub + ib + gb;
        }
        __syncthreads();   // protect s[] before next row iteration
    }
}

extern "C" void kernel_launch(void* const* d_in, const int* in_sizes, int n_in,
                              void* d_out, int out_size) {
    const int*    user_ids      = (const int*)d_in[0];
    const int*    item_ids      = (const int*)d_in[1];
    const int*    offsets       = (const int*)d_in[2];
    const int*    flat_implicit = (const int*)d_in[3];
    const float4* user_emb4     = (const float4*)d_in[4];
    const float4* item_emb4     = (const float4*)d_in[5];
    const float4* imp_emb4      = (const float4*)d_in[6];
    const float*  user_bias     = (const float*)d_in[7];
    const float*  item_bias     = (const float*)d_in[8];
    const float*  global_bias   = (const float*)d_in[9];
    float*        out           = (float*)d_out;

    const int B = in_sizes[0];          // 16384
    const int N = in_sizes[3];          // 819200

    svdpp_kernel<<<NCTA, 64>>>(user_ids, item_ids, offsets, flat_implicit,
                               user_emb4, item_emb4, imp_emb4,
                               user_bias, item_bias, global_bias,
                               out, B, N);
}

// round 9
// speedup vs baseline: 1.1152x; 1.1152x over previous
#include <cuda_runtime.h>
#include <cuda_bf16.h>

// Length-split: long rows (>LEN_T items) get 256-thread CTAs (16 slots),
// short rows get the proven 64-thread config (4 slots). Tail-free both ways.

#define LEN_T   128
#define G_LONG  2048

// ---------------- Long-row kernel: 256 thr = 16 slots x 16 lanes -----------
__global__ __launch_bounds__(256)
void svdpp_long(const int* __restrict__ user_ids,
                const int* __restrict__ item_ids,
                const int* __restrict__ offsets,
                const int* __restrict__ flat_implicit,
                const float4* __restrict__ user_emb4,
                const float4* __restrict__ item_emb4,
                const float4* __restrict__ imp_emb4,
                const float* __restrict__ user_bias,
                const float* __restrict__ item_bias,
                const float* __restrict__ global_bias,
                float* __restrict__ out,
                int B, int N) {
    const int t    = threadIdx.x;
    const int lane = t & 15;
    const int slot = t >> 4;            // 0..15
    const int warp = t >> 5;            // 0..7

    __shared__ float4 s[8][16];

    for (int b = blockIdx.x; b < B; b += G_LONG) {
        const int start = __ldg(&offsets[b]);
        const int end   = (b + 1 < B) ? __ldg(&offsets[b + 1]) : N;
        const int len   = end - start;
        if (len <= LEN_T) continue;     // uniform per block

        // Prefetch epilogue operands (latency hidden under gather).
        const int u  = __ldg(&user_ids[b]);
        const int it = __ldg(&item_ids[b]);
        const float4 u4 = __ldg(&user_emb4[(size_t)u * 16 + lane]);
        const float4 i4 = __ldg(&item_emb4[(size_t)it * 16 + lane]);
        const float  ub = __ldg(&user_bias[u]);
        const float  ib = __ldg(&item_bias[it]);
        const float  gb = __ldg(&global_bias[0]);

        float4 acc = make_float4(0.f, 0.f, 0.f, 0.f);
        int j = start + slot;
        for (; j + 48 < end; j += 64) {
            const int i0 = __ldg(&flat_implicit[j]);
            const int i1 = __ldg(&flat_implicit[j + 16]);
            const int i2 = __ldg(&flat_implicit[j + 32]);
            const int i3 = __ldg(&flat_implicit[j + 48]);
            const float4 a0 = __ldg(&imp_emb4[(size_t)i0 * 16 + lane]);
            const float4 a1 = __ldg(&imp_emb4[(size_t)i1 * 16 + lane]);
            const float4 a2 = __ldg(&imp_emb4[(size_t)i2 * 16 + lane]);
            const float4 a3 = __ldg(&imp_emb4[(size_t)i3 * 16 + lane]);
            acc.x += (a0.x + a1.x) + (a2.x + a3.x);
            acc.y += (a0.y + a1.y) + (a2.y + a3.y);
            acc.z += (a0.z + a1.z) + (a2.z + a3.z);
            acc.w += (a0.w + a1.w) + (a2.w + a3.w);
        }
        for (; j + 16 < end; j += 32) {
            const int i0 = __ldg(&flat_implicit[j]);
            const int i1 = __ldg(&flat_implicit[j + 16]);
            const float4 a0 = __ldg(&imp_emb4[(size_t)i0 * 16 + lane]);
            const float4 a1 = __ldg(&imp_emb4[(size_t)i1 * 16 + lane]);
            acc.x += a0.x + a1.x;
            acc.y += a0.y + a1.y;
            acc.z += a0.z + a1.z;
            acc.w += a0.w + a1.w;
        }
        if (j < end) {
            const float4 a = __ldg(&imp_emb4[(size_t)__ldg(&flat_implicit[j]) * 16 + lane]);
            acc.x += a.x; acc.y += a.y; acc.z += a.z; acc.w += a.w;
        }

        acc.x += __shfl_xor_sync(0xffffffffu, acc.x, 16);
        acc.y += __shfl_xor_sync(0xffffffffu, acc.y, 16);
        acc.z += __shfl_xor_sync(0xffffffffu, acc.z, 16);
        acc.w += __shfl_xor_sync(0xffffffffu, acc.w, 16);

        if ((t & 31) < 16) s[warp][lane] = acc;
        __syncthreads();

        if (t < 16) {
            float4 sum = s[0][t];
            #pragma unroll
            for (int w = 1; w < 8; ++w) {
                const float4 o = s[w][t];
                sum.x += o.x; sum.y += o.y; sum.z += o.z; sum.w += o.w;
            }
            const float invnorm = rsqrtf((float)len);   // len > LEN_T > 0
            float dot = (u4.x + sum.x * invnorm) * i4.x
                      + (u4.y + sum.y * invnorm) * i4.y
                      + (u4.z + sum.z * invnorm) * i4.z
                      + (u4.w + sum.w * invnorm) * i4.w;
            #pragma unroll
            for (int off = 8; off > 0; off >>= 1)
                dot += __shfl_down_sync(0x0000ffffu, dot, off);
            if (t == 0) out[b] = dot + ub + ib + gb;
        }
        __syncthreads();   // protect s[] for next row
    }
}

// ---------------- Short-row kernel: 64 thr = 4 slots x 16 lanes ------------
__global__ __launch_bounds__(64)
void svdpp_short(const int* __restrict__ user_ids,
                 const int* __restrict__ item_ids,
                 const int* __restrict__ offsets,
                 const int* __restrict__ flat_implicit,
                 const float4* __restrict__ user_emb4,
                 const float4* __restrict__ item_emb4,
                 const float4* __restrict__ imp_emb4,
                 const float* __restrict__ user_bias,
                 const float* __restrict__ item_bias,
                 const float* __restrict__ global_bias,
                 float* __restrict__ out,
                 int B, int N) {
    const int b    = blockIdx.x;
    const int tid  = threadIdx.x;
    const int lane = tid & 15;
    const int slot = tid >> 4;          // 0..3

    const int start = __ldg(&offsets[b]);
    const int end   = (b + 1 < B) ? __ldg(&offsets[b + 1]) : N;
    const int len   = end - start;
    if (len > LEN_T) return;            // handled by svdpp_long (uniform)

    // Prefetch epilogue operands.
    const int u  = __ldg(&user_ids[b]);
    const int it = __ldg(&item_ids[b]);
    const float4 u4 = __ldg(&user_emb4[(size_t)u * 16 + lane]);
    const float4 i4 = __ldg(&item_emb4[(size_t)it * 16 + lane]);
    const float  ub = __ldg(&user_bias[u]);
    const float  ib = __ldg(&item_bias[it]);
    const float  gb = __ldg(&global_bias[0]);

    float4 acc = make_float4(0.f, 0.f, 0.f, 0.f);
    int j = start + slot;
    for (; j + 4 < end; j += 8) {
        const int i0 = __ldg(&flat_implicit[j]);
        const int i1 = __ldg(&flat_implicit[j + 4]);
        const float4 a0 = __ldg(&imp_emb4[(size_t)i0 * 16 + lane]);
        const float4 a1 = __ldg(&imp_emb4[(size_t)i1 * 16 + lane]);
        acc.x += a0.x + a1.x;
        acc.y += a0.y + a1.y;
        acc.z += a0.z + a1.z;
        acc.w += a0.w + a1.w;
    }
    if (j < end) {
        const float4 a = __ldg(&imp_emb4[(size_t)__ldg(&flat_implicit[j]) * 16 + lane]);
        acc.x += a.x; acc.y += a.y; acc.z += a.z; acc.w += a.w;
    }

    acc.x += __shfl_xor_sync(0xffffffffu, acc.x, 16);
    acc.y += __shfl_xor_sync(0xffffffffu, acc.y, 16);
    acc.z += __shfl_xor_sync(0xffffffffu, acc.z, 16);
    acc.w += __shfl_xor_sync(0xffffffffu, acc.w, 16);

    __shared__ float4 s[16];
    if (tid >= 32 && tid < 48) s[lane] = acc;
    __syncthreads();

    if (tid < 16) {
        const float4 o = s[tid];
        acc.x += o.x; acc.y += o.y; acc.z += o.z; acc.w += o.w;

        const float invnorm = (len > 0) ? rsqrtf((float)len) : 1.0f;
        float dot = (u4.x + acc.x * invnorm) * i4.x
                  + (u4.y + acc.y * invnorm) * i4.y
                  + (u4.z + acc.z * invnorm) * i4.z
                  + (u4.w + acc.w * invnorm) * i4.w;
        #pragma unroll
        for (int off = 8; off > 0; off >>= 1)
            dot += __shfl_down_sync(0x0000ffffu, dot, off);
        if (tid == 0) out[b] = dot + ub + ib + gb;
    }
}

extern "C" void kernel_launch(void* const* d_in, const int* in_sizes, int n_in,
                              void* d_out, int out_size) {
    const int*    user_ids      = (const int*)d_in[0];
    const int*    item_ids      = (const int*)d_in[1];
    const int*    offsets       = (const int*)d_in[2];
    const int*    flat_implicit = (const int*)d_in[3];
    const float4* user_emb4     = (const float4*)d_in[4];
    const float4* item_emb4     = (const float4*)d_in[5];
    const float4* imp_emb4      = (const float4*)d_in[6];
    const float*  user_bias     = (const float*)d_in[7];
    const float*  item_bias     = (const float*)d_in[8];
    const float*  global_bias   = (const float*)d_in[9];
    float*        out           = (float*)d_out;

    const int B = in_sizes[0];          // 16384
    const int N = in_sizes[3];          // 819200

    svdpp_long<<<G_LONG, 256>>>(user_ids, item_ids, offsets, flat_implicit,
                                user_emb4, item_emb4, imp_emb4,
                                user_bias, item_bias, global_bias, out, B, N);

    svdpp_short<<<B, 64>>>(user_ids, item_ids, offsets, flat_implicit,
                           user_emb4, item_emb4, imp_emb4,
                           user_bias, item_bias, global_bias, out, B, N);
}